// round 12
// baseline (speedup 1.0000x reference)
#include <cuda_runtime.h>
#include <cuda_fp16.h>
#include <stdint.h>

// LSTM B=128,T=256,H=1024,C=10 — persistent mma.sync kernel.
// R12: split-K dual-team. Warps 0-7 (team0) k=[0,512), warps 8-15 (team1)
// k=[512,1024), warp 16 lane 0 = producer. Two independent 3-deep bulk rings,
// per-Mtile partial combine via SMEM + named barriers. KC=64.

#define BB   128
#define TT   256
#define HH   1024
#define CC   10
#define NCTA 128
#define NTHR 544        // 16 compute warps + 1 producer warp
#define NWC  8          // warps per team
#define JPC  8          // hidden units per CTA (32 gate rows)
#define KC   64         // K per staged chunk
#define NCHT 8          // chunks per team per step
#define NBUF 3

// ---- SMEM layout (byte offsets from 128B-aligned base) ----
#define A_BASE  65536                   // W occupies [0, 65536)
#define A_BUF   16384                   // one buffer: 64 k-rows * 256B
#define A_T1    (A_BASE + NBUF*A_BUF)   // team1 ring base = 114688
#define SM_PD   (A_T1 + NBUF*A_BUF)     // 163840, partial-D: 16 KB
#define MISC    (SM_PD + 16384)         // 180224
#define SM_XW   (MISC)
#define SM_BS   (MISC + 128)
#define SM_FULL0 (MISC + 256)           // 3 x 8B
#define SM_FULL1 (MISC + 256 + 24)      // 3 x 8B
#define SM_EMPT0 (MISC + 256 + 48)      // 3 x 8B
#define SM_EMPT1 (MISC + 256 + 72)      // 3 x 8B
#define SM_EPI   (MISC + 256 + 96)      // 8B
#define SMEM_DYN (MISC + 512)

typedef unsigned short ushort_t;

// h plane, k-major: byte(k,b) = k*256 + (((b>>3)^(k&7))<<4) + ((b&7)<<1)
__device__ __align__(128) __half g_hh[2][HH * BB];
__device__ unsigned g_bar;

__global__ void reset_kernel() { g_bar = 0u; }

// ---------------- helpers ----------------
__device__ __forceinline__ uint32_t s2u(const void* p) {
    uint32_t a;
    asm("{ .reg .u64 t; cvta.to.shared.u64 t, %1; cvt.u32.u64 %0, t; }"
        : "=r"(a) : "l"(p));
    return a;
}

#define LDM4(r, addr) \
    asm volatile("ldmatrix.sync.aligned.m8n8.x4.shared.b16 {%0,%1,%2,%3}, [%4];" \
                 : "=r"((r)[0]), "=r"((r)[1]), "=r"((r)[2]), "=r"((r)[3]) \
                 : "r"(addr))

#define LDM4T(r, addr) \
    asm volatile("ldmatrix.sync.aligned.m8n8.x4.trans.shared.b16 {%0,%1,%2,%3}, [%4];" \
                 : "=r"((r)[0]), "=r"((r)[1]), "=r"((r)[2]), "=r"((r)[3]) \
                 : "r"(addr))

#define MMA(d, a, b0_, b1_) \
    asm volatile("mma.sync.aligned.m16n8k16.row.col.f32.f16.f16.f32 " \
                 "{%0,%1,%2,%3}, {%4,%5,%6,%7}, {%8,%9}, {%0,%1,%2,%3};" \
                 : "+f"((d)[0]), "+f"((d)[1]), "+f"((d)[2]), "+f"((d)[3]) \
                 : "r"((a)[0]), "r"((a)[1]), "r"((a)[2]), "r"((a)[3]), \
                   "r"(b0_), "r"(b1_))

#define BARPAIR(id) \
    asm volatile("bar.sync %0, 64;" :: "r"(id) : "memory")

__device__ __forceinline__ void mbar_init(uint32_t mbar, uint32_t cnt) {
    asm volatile("mbarrier.init.shared.b64 [%0], %1;" :: "r"(mbar), "r"(cnt) : "memory");
}
__device__ __forceinline__ void mbar_expect_tx(uint32_t mbar, uint32_t bytes) {
    asm volatile("mbarrier.arrive.expect_tx.shared.b64 _, [%0], %1;"
                 :: "r"(mbar), "r"(bytes) : "memory");
}
__device__ __forceinline__ void mbar_arrive(uint32_t mbar) {
    asm volatile("mbarrier.arrive.shared.b64 _, [%0];" :: "r"(mbar) : "memory");
}
__device__ __forceinline__ void bulk_g2s(uint32_t dst, const void* src,
                                         uint32_t bytes, uint32_t mbar) {
    asm volatile("cp.async.bulk.shared::cluster.global.mbarrier::complete_tx::bytes "
                 "[%0], [%1], %2, [%3];"
                 :: "r"(dst), "l"(src), "r"(bytes), "r"(mbar) : "memory");
}
__device__ __forceinline__ void mbar_wait(uint32_t mbar, uint32_t parity) {
    uint32_t done;
    asm volatile(
        "{\n\t.reg .pred p;\n\t"
        "mbarrier.try_wait.parity.acquire.cta.shared::cta.b64 p, [%1], %2;\n\t"
        "selp.b32 %0, 1, 0, p;\n\t}"
        : "=r"(done) : "r"(mbar), "r"(parity) : "memory");
    if (!done) {
        asm volatile(
            "{\n\t.reg .pred P1;\n\t"
            "WL_%=:\n\t"
            "mbarrier.try_wait.parity.acquire.cta.shared::cta.b64 P1, [%0], %1, 0x989680;\n\t"
            "@P1 bra.uni WD_%=;\n\t"
            "bra.uni WL_%=;\n\t"
            "WD_%=:\n\t}"
            :: "r"(mbar), "r"(parity) : "memory");
    }
}
__device__ __forceinline__ void fence_proxy_async_() {
    asm volatile("fence.proxy.async;" ::: "memory");
}
__device__ __forceinline__ ushort_t hfu(__half v) { return __half_as_ushort(v); }

// ---------------- main LSTM kernel ----------------
__global__ void __launch_bounds__(NTHR, 1) lstm_kernel(
    const float* __restrict__ x,
    const float* __restrict__ Wgx, const float* __restrict__ Wgh, const float* __restrict__ bg,
    const float* __restrict__ Wix, const float* __restrict__ Wih, const float* __restrict__ bi,
    const float* __restrict__ Wfx, const float* __restrict__ Wfh, const float* __restrict__ bf,
    const float* __restrict__ Wox, const float* __restrict__ Woh, const float* __restrict__ bo)
{
    extern __shared__ char smraw[];
    const uint32_t rawu = s2u(smraw);
    const uint32_t sb = (rawu + 127u) & ~127u;
    char* smem = smraw + (sb - rawu);

    const int tid  = threadIdx.x;
    const int lane = tid & 31;
    const int warp = tid >> 5;
    const int j0   = blockIdx.x * JPC;

    // ---- one-time: W (fp16) -> SMEM ktile layout with (n&4) flip ----
    {
        const float* Wh[4] = {Wgh, Wih, Wfh, Woh};
        for (int idx = tid; idx < 32 * HH; idx += NTHR) {
            int n = idx >> 10, k = idx & (HH - 1);
            float w = Wh[n >> 3][(size_t)(j0 + (n & 7)) * HH + k];
            uint32_t off = (uint32_t)(k >> 4) * 1024u + (uint32_t)n * 32u
                         + (((uint32_t)(k & 15) * 2u) ^ (((uint32_t)n & 4u) << 2));
            *(ushort_t*)(smem + off) = hfu(__float2half(w));
        }
    }
    float* s_xw = (float*)(smem + SM_XW);
    float* s_bs = (float*)(smem + SM_BS);
    if (tid < 8) {
        s_xw[tid]      = Wgx[j0 + tid];  s_xw[8 + tid]  = Wix[j0 + tid];
        s_xw[16 + tid] = Wfx[j0 + tid];  s_xw[24 + tid] = Wox[j0 + tid];
        s_bs[tid]      = bg[j0 + tid];   s_bs[8 + tid]  = bi[j0 + tid];
        s_bs[16 + tid] = bf[j0 + tid];   s_bs[24 + tid] = bo[j0 + tid];
    }
    if (tid == 0) {
#pragma unroll
        for (int i = 0; i < NBUF; ++i) {
            mbar_init(sb + SM_FULL0 + (uint32_t)i * 8u, 1);
            mbar_init(sb + SM_FULL1 + (uint32_t)i * 8u, 1);
            mbar_init(sb + SM_EMPT0 + (uint32_t)i * 8u, NWC);
            mbar_init(sb + SM_EMPT1 + (uint32_t)i * 8u, NWC);
        }
        mbar_init(sb + SM_EPI, NWC);
    }
    __syncthreads();

    if (warp < 16) {
        // ================= COMPUTE WARPS =================
        const int team = warp >> 3;          // 0: k[0,512), 1: k[512,1024)
        const int m    = warp & 7;           // M-tile index (batch rows m*16..)
        const uint32_t aRing = sb + (team ? A_T1 : A_BASE);
        const uint32_t fullB = sb + (team ? SM_FULL1 : SM_FULL0);
        const uint32_t emptB = sb + (team ? SM_EMPT1 : SM_EMPT0);
        const uint32_t pdB   = sb + SM_PD + (uint32_t)m * 2048u + (uint32_t)lane * 16u;

        uint32_t aBase;
        {
            uint32_t kkb = (((uint32_t)lane & 16u) >> 1) + ((uint32_t)lane & 7u);
            uint32_t bgr = (uint32_t)m * 2u + (((uint32_t)lane >> 3) & 1u);
            uint32_t sw  = (bgr ^ ((uint32_t)lane & 7u)) << 4;
            aBase = aRing + kkb * 256u + sw;
        }
        uint32_t bAddr[2];
#pragma unroll
        for (int p = 0; p < 2; ++p) {
            int n = p * 16 + ((lane >> 4) << 3) + (lane & 7);
            bAddr[p] = sb + (uint32_t)n * 32
                     + (((uint32_t)((lane >> 3) & 1) * 16) ^ (((uint32_t)n & 4) << 2));
        }
        const uint32_t wBase = (uint32_t)team * 32768u;   // team1: ktiles 32..63

        float cst[2][2];
#pragma unroll
        for (int rr = 0; rr < 2; ++rr) { cst[rr][0] = 0.0f; cst[rr][1] = 0.0f; }

        const int u0 = (lane & 3) * 2;
        int cs = 0; unsigned cph = 0;

        for (int t = 0; t < TT; ++t) {
            float D[4][4];
#pragma unroll
            for (int nt = 0; nt < 4; ++nt)
#pragma unroll
                for (int e = 0; e < 4; ++e) D[nt][e] = 0.0f;

            if (t > 0) {
                for (int ch = 0; ch < NCHT; ++ch) {
                    mbar_wait(fullB + (uint32_t)cs * 8u, cph);
                    const uint32_t boff = (uint32_t)cs * A_BUF;
#pragma unroll
                    for (int q = 0; q < 4; ++q) {
                        const uint32_t ao = aBase + boff + (uint32_t)q * 4096u;
                        const uint32_t wo = wBase + (uint32_t)(ch * 4 + q) * 1024u;
                        uint32_t ah[4];
                        uint32_t b0[4], b1[4];
                        LDM4T(ah, ao);
                        LDM4(b0, bAddr[0] + wo);
                        LDM4(b1, bAddr[1] + wo);
                        MMA(D[0], ah, b0[0], b0[1]);
                        MMA(D[1], ah, b0[2], b0[3]);
                        MMA(D[2], ah, b1[0], b1[1]);
                        MMA(D[3], ah, b1[2], b1[3]);
                    }
                    if (lane == 0) mbar_arrive(emptB + (uint32_t)cs * 8u);
                    if (++cs == NBUF) { cs = 0; cph ^= 1; }
                }
            }

            if (team == 1) {
                // dump partial D, handoff to team0 partner
#pragma unroll
                for (int nt = 0; nt < 4; ++nt) {
                    float4 v = make_float4(D[nt][0], D[nt][1], D[nt][2], D[nt][3]);
                    *(float4*)(smem + (pdB - sb) + (uint32_t)nt * 512u) = v;
                }
                BARPAIR(1 + m);
                continue;
            }

            // team0: merge partner partial, then epilogue
            BARPAIR(1 + m);
#pragma unroll
            for (int nt = 0; nt < 4; ++nt) {
                float4 v = *(const float4*)(smem + (pdB - sb) + (uint32_t)nt * 512u);
                D[nt][0] += v.x; D[nt][1] += v.y; D[nt][2] += v.z; D[nt][3] += v.w;
            }

            char* hdst = (char*)g_hh[t & 1];
#pragma unroll
            for (int rr = 0; rr < 2; ++rr) {
                const int b = m * 16 + rr * 8 + (lane >> 2);
                const float xv = x[b * TT + t];
#pragma unroll
                for (int uu = 0; uu < 2; ++uu) {
                    const int u = u0 + uu;
                    const int e = rr * 2 + uu;
                    float zg = D[0][e] + xv * s_xw[u]      + s_bs[u];
                    float zi = D[1][e] + xv * s_xw[8 + u]  + s_bs[8 + u];
                    float zf = D[2][e] + xv * s_xw[16 + u] + s_bs[16 + u];
                    float zo = D[3][e] + xv * s_xw[24 + u] + s_bs[24 + u];
                    float gg = tanhf(zg);
                    float ii = 1.0f / (1.0f + __expf(-zi));
                    float ff = 1.0f / (1.0f + __expf(-zf));
                    float oo = 1.0f / (1.0f + __expf(-zo));
                    float c  = cst[rr][uu];
                    c = gg * ii + c * ff;
                    cst[rr][uu] = c;
                    float hn = tanhf(c) * oo;
                    const int kA = j0 + u;
                    const size_t off = (size_t)kA * 256
                                     + (size_t)((((unsigned)b >> 3) ^ ((unsigned)u & 7u)) << 4)
                                     + (size_t)(((unsigned)b & 7u) << 1);
                    *(ushort_t*)(hdst + off) = hfu(__float2half(hn));
                }
            }
            __threadfence();
            if (lane == 0) mbar_arrive(sb + SM_EPI);
        }
    } else if (tid == 512) {
        // ================= PRODUCER THREAD =================
        int ps0 = 0, ps1 = 0; unsigned pp0 = 1, pp1 = 1;
        for (int t = 1; t < TT; ++t) {
            mbar_wait(sb + SM_EPI, (unsigned)(t - 1) & 1u);
            __threadfence();
            atomicAdd(&g_bar, 1u);
            const unsigned tgt = (unsigned)t * NCTA;
            while (*(volatile unsigned*)&g_bar < tgt) { __nanosleep(32); }
            __threadfence();
            fence_proxy_async_();
            const char* hsrc = (const char*)g_hh[(t - 1) & 1];
            for (int i = 0; i < NCHT; ++i) {
                // ring0: chunk i (k = i*64 ..)
                mbar_wait(sb + SM_EMPT0 + (uint32_t)ps0 * 8u, pp0);
                {
                    const uint32_t mb  = sb + SM_FULL0 + (uint32_t)ps0 * 8u;
                    const uint32_t dst = sb + A_BASE + (uint32_t)ps0 * A_BUF;
                    mbar_expect_tx(mb, A_BUF);
                    bulk_g2s(dst, hsrc + (size_t)i * A_BUF, A_BUF, mb);
                }
                if (++ps0 == NBUF) { ps0 = 0; pp0 ^= 1; }
                // ring1: chunk 8+i (k = 512 + i*64 ..)
                mbar_wait(sb + SM_EMPT1 + (uint32_t)ps1 * 8u, pp1);
                {
                    const uint32_t mb  = sb + SM_FULL1 + (uint32_t)ps1 * 8u;
                    const uint32_t dst = sb + A_T1 + (uint32_t)ps1 * A_BUF;
                    mbar_expect_tx(mb, A_BUF);
                    bulk_g2s(dst, hsrc + (size_t)(NCHT + i) * A_BUF, A_BUF, mb);
                }
                if (++ps1 == NBUF) { ps1 = 0; pp1 ^= 1; }
            }
        }
    }
}

// ---------------- projection ----------------
__global__ void proj_kernel(const float* __restrict__ Wp,
                            const float* __restrict__ bp,
                            float* __restrict__ out)
{
    __shared__ float red[256][CC];
    const int b = blockIdx.x;
    const int tid = threadIdx.x;
    const char* hs = (const char*)g_hh[(TT - 1) & 1];

    float p[CC];
#pragma unroll
    for (int c = 0; c < CC; ++c) p[c] = 0.0f;
    for (int k = tid; k < HH; k += 256) {
        const size_t off = (size_t)k * 256
                         + (size_t)((((unsigned)b >> 3) ^ ((unsigned)k & 7u)) << 4)
                         + (size_t)(((unsigned)b & 7u) << 1);
        float hv = __half2float(__ushort_as_half(*(const ushort_t*)(hs + off)));
#pragma unroll
        for (int c = 0; c < CC; ++c) p[c] += hv * Wp[k * CC + c];
    }
#pragma unroll
    for (int c = 0; c < CC; ++c) red[tid][c] = p[c];
    __syncthreads();
    if (tid < CC) {
        float s = 0.0f;
        for (int i = 0; i < 256; ++i) s += red[i][tid];
        out[b * CC + tid] = s + bp[tid];
    }
}

extern "C" void kernel_launch(void* const* d_in, const int* in_sizes, int n_in,
                              void* d_out, int out_size)
{
    (void)in_sizes; (void)n_in; (void)out_size;
    const float* x   = (const float*)d_in[0];
    const float* Wgx = (const float*)d_in[1];
    const float* Wgh = (const float*)d_in[2];
    const float* bg  = (const float*)d_in[3];
    const float* Wix = (const float*)d_in[4];
    const float* Wih = (const float*)d_in[5];
    const float* bi  = (const float*)d_in[6];
    const float* Wfx = (const float*)d_in[7];
    const float* Wfh = (const float*)d_in[8];
    const float* bf  = (const float*)d_in[9];
    const float* Wox = (const float*)d_in[10];
    const float* Woh = (const float*)d_in[11];
    const float* bo  = (const float*)d_in[12];
    const float* Wp  = (const float*)d_in[13];
    const float* bp  = (const float*)d_in[14];

    cudaFuncSetAttribute(lstm_kernel,
                         cudaFuncAttributeMaxDynamicSharedMemorySize, SMEM_DYN);

    reset_kernel<<<1, 1>>>();
    lstm_kernel<<<NCTA, NTHR, SMEM_DYN>>>(x, Wgx, Wgh, bg, Wix, Wih, bi,
                                          Wfx, Wfh, bf, Wox, Woh, bo);
    proj_kernel<<<BB, 256>>>(Wp, bp, (float*)d_out);
}